// round 3
// baseline (speedup 1.0000x reference)
#include <cuda_runtime.h>
#include <float.h>

typedef unsigned long long ull;

#define NB   8
#define NLQ  512
#define NL   4096
#define ND   64
#define TQ   8
#define TK   128
#define KSTR 68
#define NTHREADS 512
#define NTILES (NL/TK)

// smem layout (floats)
#define OFF_SC    0                        // TQ*NL   = 32768
#define OFF_KS    (OFF_SC  + TQ*NL)        // TK*KSTR = 8704
#define OFF_VS    (OFF_KS  + TK*KSTR)      // TK*KSTR = 8704
#define OFF_MS    (OFF_VS  + TK*KSTR)      // TQ*TK   = 1024
#define OFF_QT    (OFF_MS  + TQ*TK)        // ND*TQ   = 512 (transposed q)
#define OFF_MSUM  (OFF_QT  + ND*TQ)        // TQ*ND   = 512
#define OFF_CNT   (OFF_MSUM+ TQ*ND)        // TQ
#define SMEM_FLOATS (OFF_CNT + TQ)
#define SMEM_BYTES  (SMEM_FLOATS * 4)

// packed fp32x2 ops (sm_103a)
#define F32X2_FMA(d,a,b)  asm("fma.rn.f32x2 %0, %1, %2, %0;" : "+l"(d) : "l"(a), "l"(b))
#define F32X2_ADD(d,a,b)  asm("add.rn.f32x2 %0, %1, %2;"     : "=l"(d) : "l"(a), "l"(b))
#define F32X2_PACK(d,lo,hi)   asm("mov.b64 %0, {%1, %2};" : "=l"(d) : "f"(lo), "f"(hi))
#define F32X2_UNPACK(lo,hi,s) asm("mov.b64 {%0, %1}, %2;" : "=f"(lo), "=f"(hi) : "l"(s))

__device__ int g_mask_mode;   // 0 = uint8, 1 = int32, 2 = float32

__global__ void detect_mask_kernel(const unsigned int* __restrict__ m) {
    int allle1 = 1, allf = 1;
    for (int i = 0; i < 32; ++i) {
        unsigned w = m[i];
        if (w > 1u) allle1 = 0;
        if (w != 0u && w != 0x3F800000u) allf = 0;
    }
    g_mask_mode = allf ? 2 : (allle1 ? 1 : 0);
}

__global__ __launch_bounds__(NTHREADS, 1)
void ga_kernel(const float* __restrict__ qg, const float* __restrict__ kg,
               const float* __restrict__ vg, const void* __restrict__ maskg,
               float* __restrict__ out)
{
    extern __shared__ float smem[];
    float* sc   = smem + OFF_SC;
    float* k_s  = smem + OFF_KS;
    float* v_s  = smem + OFF_VS;
    float* m_s  = smem + OFF_MS;
    float* qT   = smem + OFF_QT;
    float* msum = smem + OFF_MSUM;
    float* cnts = smem + OFF_CNT;

    const int t    = threadIdx.x;
    const int wid  = t >> 5;
    const int lane = t & 31;
    const int b    = blockIdx.x >> 6;
    const int q0   = (blockIdx.x & 63) * TQ;
    const int mode = g_mask_mode;

    // stage Q transposed: qT[d*8+q]
    {
        int d = t >> 3, q = t & 7;
        qT[t] = qg[((size_t)(b * NLQ + q0 + q)) * ND + d];
    }

    const float4* kg4 = (const float4*)(kg + (size_t)b * NL * ND);
    const float4* vg4 = (const float4*)(vg + (size_t)b * NL * ND);

    float4 kr[4], vr[4];
    float4 mv = make_float4(0.f, 0.f, 0.f, 0.f);

    const int fl[4]  = { (t) >> 4, (t + 512) >> 4, (t + 1024) >> 4, (t + 1536) >> 4 };
    const int fd4    = t & 15;
    const int mqq    = t >> 5;          // t<256 only
    const int mli4   = (t & 31) * 4;

    auto LOADT = [&](int tile) {
        const int l0t = tile * TK;
        #pragma unroll
        for (int it = 0; it < 4; ++it) {
            kr[it] = kg4[(size_t)(l0t + fl[it]) * 16 + fd4];
            vr[it] = vg4[(size_t)(l0t + fl[it]) * 16 + fd4];
        }
        if (t < 256) {
            size_t base = ((size_t)(b * NLQ + q0 + mqq)) * NL + l0t + mli4;
            if (mode == 0) {
                uchar4 u = *(const uchar4*)((const unsigned char*)maskg + base);
                mv = make_float4(u.x ? 1.f : 0.f, u.y ? 1.f : 0.f,
                                 u.z ? 1.f : 0.f, u.w ? 1.f : 0.f);
            } else if (mode == 1) {
                int4 u = *(const int4*)((const int*)maskg + base);
                mv = make_float4(u.x ? 1.f : 0.f, u.y ? 1.f : 0.f,
                                 u.z ? 1.f : 0.f, u.w ? 1.f : 0.f);
            } else {
                mv = *(const float4*)((const float*)maskg + base);
            }
        }
    };
    auto STORET = [&]() {
        #pragma unroll
        for (int it = 0; it < 4; ++it) {
            *(float4*)(k_s + fl[it] * KSTR + 4 * fd4) = kr[it];
            *(float4*)(v_s + fl[it] * KSTR + 4 * fd4) = vr[it];
        }
        if (t < 256) *(float4*)(m_s + mqq * TK + mli4) = mv;
    };

    LOADT(0);

    float c0 = 0.f, c1 = 0.f;   // gather result (score warps)

    if (wid < 8) {
        // ================= score path: warp owns 16 keys, all 8 queries ====
        const int li   = lane & 15;
        const int half = lane >> 4;
        const int l    = wid * 16 + li;
        const int db   = half * 32;

        for (int tile = 0; tile < NTILES; ++tile) {
            __syncthreads();
            STORET();
            if (tile + 1 < NTILES) LOADT(tile + 1);
            __syncthreads();

            ull a01 = 0, a23 = 0, a45 = 0, a67 = 0;
            const float* krow = k_s + l * KSTR + db;
            const float* qTd  = qT + db * 8;
            #pragma unroll
            for (int s = 0; s < 8; ++s) {
                float4 k4 = *(const float4*)(krow + 4 * s);
                #pragma unroll
                for (int j = 0; j < 4; ++j) {
                    float kd = (j == 0) ? k4.x : (j == 1) ? k4.y : (j == 2) ? k4.z : k4.w;
                    const float* qrow = qTd + (4 * s + j) * 8;
                    ulonglong2 qA = *(const ulonglong2*)qrow;
                    ulonglong2 qB = *(const ulonglong2*)(qrow + 4);
                    ull kk; F32X2_PACK(kk, kd, kd);
                    F32X2_FMA(a01, kk, qA.x);
                    F32X2_FMA(a23, kk, qA.y);
                    F32X2_FMA(a45, kk, qB.x);
                    F32X2_FMA(a67, kk, qB.y);
                }
            }
            // combine d-halves
            ull o;
            o = __shfl_xor_sync(0xffffffffu, a01, 16); F32X2_ADD(a01, a01, o);
            o = __shfl_xor_sync(0xffffffffu, a23, 16); F32X2_ADD(a23, a23, o);
            o = __shfl_xor_sync(0xffffffffu, a45, 16); F32X2_ADD(a45, a45, o);
            o = __shfl_xor_sync(0xffffffffu, a67, 16); F32X2_ADD(a67, a67, o);

            // lanes<16 write q0..3, lanes>=16 write q4..7
            const int qb = half * 4;
            ull pA = half ? a45 : a01;
            ull pB = half ? a67 : a23;
            float f0, f1, f2, f3;
            F32X2_UNPACK(f0, f1, pA);
            F32X2_UNPACK(f2, f3, pB);
            const int l0 = tile * TK;
            float m0 = m_s[(qb + 0) * TK + l];
            float m1 = m_s[(qb + 1) * TK + l];
            float m2 = m_s[(qb + 2) * TK + l];
            float m3 = m_s[(qb + 3) * TK + l];
            sc[(qb + 0) * NL + l0 + l] = (m0 != 0.f) ? f0 * 0.125f : -FLT_MAX;
            sc[(qb + 1) * NL + l0 + l] = (m1 != 0.f) ? f1 * 0.125f : -FLT_MAX;
            sc[(qb + 2) * NL + l0 + l] = (m2 != 0.f) ? f2 * 0.125f : -FLT_MAX;
            sc[(qb + 3) * NL + l0 + l] = (m3 != 0.f) ? f3 * 0.125f : -FLT_MAX;
        }

        // ================= top-32 + softmax + gather for query q=wid =======
        const int q = wid;
        const float* row = sc + q * NL;

        float v0 = -FLT_MAX, v1 = -FLT_MAX, v2 = -FLT_MAX, v3 = -FLT_MAX;
        int   i0 = NL, i1 = NL, i2 = NL, i3 = NL;
        for (int i = lane; i < NL; i += 32) {
            float x = row[i];
            if (x > v3) {
                if (x > v1) {
                    if (x > v0) { v3=v2;i3=i2; v2=v1;i2=i1; v1=v0;i1=i0; v0=x;i0=i; }
                    else        { v3=v2;i3=i2; v2=v1;i2=i1; v1=x;i1=i; }
                } else {
                    if (x > v2) { v3=v2;i3=i2; v2=x;i2=i; }
                    else        { v3=x;i3=i; }
                }
            }
        }

        float myval = -FLT_MAX;
        int   myidx = NL;
        for (int s = 0; s < 32; ++s) {
            float cv = v0; int ci = i0;
            #pragma unroll
            for (int off = 16; off; off >>= 1) {
                float ov = __shfl_xor_sync(0xffffffffu, cv, off);
                int   oi = __shfl_xor_sync(0xffffffffu, ci, off);
                if (ov > cv || (ov == cv && oi < ci)) { cv = ov; ci = oi; }
            }
            if (lane == s) { myval = cv; myidx = ci; }
            if (v0 == cv && i0 == ci) {
                v0 = v1; i0 = i1; v1 = v2; i1 = i2; v2 = v3; i2 = i3;
                v3 = -FLT_MAX; i3 = NL;
                if (v0 == -FLT_MAX && cv > -FLT_MAX) {
                    float nv = -FLT_MAX; int ni = NL;
                    for (int i = lane; i < NL; i += 32) {
                        float x = row[i];
                        if (x < cv && x > nv) { nv = x; ni = i; }
                    }
                    v0 = nv; i0 = ni;
                }
            }
        }

        bool  valid = (myval > -1e37f) && (myidx < NL);
        float mmax  = valid ? myval : -FLT_MAX;
        #pragma unroll
        for (int off = 16; off; off >>= 1)
            mmax = fmaxf(mmax, __shfl_xor_sync(0xffffffffu, mmax, off));
        float e  = valid ? __expf(myval - mmax) : 0.f;
        float es = e;
        #pragma unroll
        for (int off = 16; off; off >>= 1)
            es += __shfl_xor_sync(0xffffffffu, es, off);
        float attn = (es > 0.f) ? e / es : 0.f;

        const float* vb = vg + (size_t)b * NL * ND;
        #pragma unroll 4
        for (int i = 0; i < 32; ++i) {
            float a   = __shfl_sync(0xffffffffu, attn,  i);
            int   idx = __shfl_sync(0xffffffffu, myidx, i);
            if (a > 0.f && idx < NL) {
                const float* vr2 = vb + (size_t)idx * ND;
                c0 += a * vr2[lane];
                c1 += a * vr2[lane + 32];
            }
        }
        __syncthreads();   // wait for msum/cnts from mean warps
    } else {
        // ================= mean path: warp owns 16 keys ====================
        const int wm    = wid - 8;
        const int c     = lane & 15;
        const int half  = lane >> 4;
        const int lbase = wm * 16;

        ull   accA[8], accB[8];
        float cq[8];
        #pragma unroll
        for (int q = 0; q < 8; ++q) { accA[q] = 0; accB[q] = 0; cq[q] = 0.f; }

        for (int tile = 0; tile < NTILES; ++tile) {
            __syncthreads();
            STORET();
            if (tile + 1 < NTILES) LOADT(tile + 1);
            __syncthreads();

            #pragma unroll
            for (int s = 0; s < 8; ++s) {
                const int l = lbase + 2 * s + half;
                ulonglong2 vp = *(const ulonglong2*)(v_s + l * KSTR + 4 * c);
                const float* mrow = m_s + l;
                #pragma unroll
                for (int q = 0; q < 8; ++q) {
                    float m = mrow[q * TK];
                    ull mm; F32X2_PACK(mm, m, m);
                    F32X2_FMA(accA[q], mm, vp.x);
                    F32X2_FMA(accB[q], mm, vp.y);
                    if (c == 0) cq[q] += m;
                }
            }
        }
        // combine l-parity halves
        #pragma unroll
        for (int q = 0; q < 8; ++q) {
            ull o;
            o = __shfl_xor_sync(0xffffffffu, accA[q], 16); F32X2_ADD(accA[q], accA[q], o);
            o = __shfl_xor_sync(0xffffffffu, accB[q], 16); F32X2_ADD(accB[q], accB[q], o);
            cq[q] += __shfl_xor_sync(0xffffffffu, cq[q], 16);
        }
        // write per-warp partials into this warp's own (dead) v_s rows
        float* pbuf = v_s + wm * 1088;
        if (half == 0) {
            #pragma unroll
            for (int q = 0; q < 8; ++q) {
                float f0, f1, f2, f3;
                F32X2_UNPACK(f0, f1, accA[q]);
                F32X2_UNPACK(f2, f3, accB[q]);
                *(float4*)(pbuf + q * ND + 4 * c) = make_float4(f0, f1, f2, f3);
            }
            if (c == 0) {
                #pragma unroll
                for (int q = 0; q < 8; ++q) pbuf[512 + q] = cq[q];
            }
        }
        asm volatile("bar.sync 1, 256;" ::: "memory");
        // reduce 8 warp-partials -> msum / cnts
        const int idx = wm * 32 + lane;   // 0..255
        #pragma unroll
        for (int r = 0; r < 2; ++r) {
            const int j = idx * 2 + r;
            float s = 0.f;
            #pragma unroll
            for (int p = 0; p < 8; ++p) s += v_s[p * 1088 + j];
            msum[j] = s;
        }
        if (idx < 8) {
            float s = 0.f;
            #pragma unroll
            for (int p = 0; p < 8; ++p) s += v_s[p * 1088 + 512 + idx];
            cnts[idx] = s;
        }
        __syncthreads();
    }

    // ================= epilogue ============================================
    if (wid < 8) {
        const int q = wid;
        float cdiv = fmaxf(cnts[q], 1.f);
        size_t orow = ((size_t)(b * NLQ + q0 + q)) * ND;
        out[orow + lane]      = msum[q * ND + lane]      / cdiv + c0;
        out[orow + lane + 32] = msum[q * ND + lane + 32] / cdiv + c1;
    }
}

extern "C" void kernel_launch(void* const* d_in, const int* in_sizes, int n_in,
                              void* d_out, int out_size) {
    const float* q    = (const float*)d_in[0];
    const float* k    = (const float*)d_in[1];
    const float* v    = (const float*)d_in[2];
    const void*  mask = d_in[3];
    float* out = (float*)d_out;

    cudaFuncSetAttribute(ga_kernel, cudaFuncAttributeMaxDynamicSharedMemorySize,
                         SMEM_BYTES);

    detect_mask_kernel<<<1, 1>>>((const unsigned int*)mask);
    ga_kernel<<<NB * (NLQ / TQ), NTHREADS, SMEM_BYTES>>>(q, k, v, mask, out);
}

// round 4
// speedup vs baseline: 1.0364x; 1.0364x over previous
#include <cuda_runtime.h>
#include <float.h>

typedef unsigned long long ull;

#define NB   8
#define NLQ  512
#define NL   4096
#define ND   64
#define TQ   8
#define TK   128
#define NTHREADS 512
#define NTILES (NL/TK)
#define NCTAS  (NB * (NLQ/TQ))     // 512

#define KSTR 72          // split-d row: d<32 at [d], d>=32 at [36+(d-32)]
#define MSTR 132         // mask row stride
#define QTH  392         // qT d-half block stride (32*12 + 8)

// smem offsets (floats)
#define OFF_KS   0
#define OFF_VS   (OFF_KS + TK*KSTR)        // 9216
#define OFF_MS   (OFF_VS + TK*KSTR)        // 18432
#define OFF_QT   (OFF_MS + TQ*MSTR)        // 19488
#define OFF_MSUM (OFF_QT + 2*QTH)          // 20272
#define OFF_CNT  (OFF_MSUM + TQ*ND)        // 20784
#define SMEM_FLOATS (OFF_CNT + TQ)         // 20792
#define SMEM_BYTES  (SMEM_FLOATS * 4)      // 83168 B -> 2 CTAs/SM

// packed fp32x2 ops (sm_103a)
#define F32X2_FMA(d,a,b)  asm("fma.rn.f32x2 %0, %1, %2, %0;" : "+l"(d) : "l"(a), "l"(b))
#define F32X2_ADD(d,a,b)  asm("add.rn.f32x2 %0, %1, %2;"     : "=l"(d) : "l"(a), "l"(b))
#define F32X2_PACK(d,lo,hi)   asm("mov.b64 %0, {%1, %2};" : "=l"(d) : "f"(lo), "f"(hi))
#define F32X2_UNPACK(lo,hi,s) asm("mov.b64 {%0, %1}, %2;" : "=f"(lo), "=f"(hi) : "l"(s))

// global score scratch: 512 CTAs x 8 q x 4096 keys = 64 MB (L2-resident)
__device__ float g_sc[(size_t)NCTAS * TQ * NL];

__device__ int g_mask_mode;   // 0 = uint8, 1 = int32, 2 = float32

__global__ void detect_mask_kernel(const unsigned int* __restrict__ m) {
    int allle1 = 1, allf = 1;
    for (int i = 0; i < 32; ++i) {
        unsigned w = m[i];
        if (w > 1u) allle1 = 0;
        if (w != 0u && w != 0x3F800000u) allf = 0;
    }
    g_mask_mode = allf ? 2 : (allle1 ? 1 : 0);
}

__global__ __launch_bounds__(NTHREADS, 2)
void ga_kernel(const float* __restrict__ qg, const float* __restrict__ kg,
               const float* __restrict__ vg, const void* __restrict__ maskg,
               float* __restrict__ out)
{
    extern __shared__ float smem[];
    float* k_s  = smem + OFF_KS;
    float* v_s  = smem + OFF_VS;
    float* m_s  = smem + OFF_MS;
    float* qT   = smem + OFF_QT;
    float* msum = smem + OFF_MSUM;
    float* cnts = smem + OFF_CNT;

    const int t    = threadIdx.x;
    const int wid  = t >> 5;
    const int lane = t & 31;
    const int b    = blockIdx.x >> 6;
    const int q0   = (blockIdx.x & 63) * TQ;
    const int mode = g_mask_mode;

    float* gsc = g_sc + (size_t)blockIdx.x * (TQ * NL);

    // stage Q: qT[dh*QTH + (d&31)*12 + q]
    {
        int d = t >> 3, q = t & 7;
        qT[(d >> 5) * QTH + (d & 31) * 12 + q] =
            qg[((size_t)(b * NLQ + q0 + q)) * ND + d];
    }

    const float4* kg4 = (const float4*)(kg + (size_t)b * NL * ND);
    const float4* vg4 = (const float4*)(vg + (size_t)b * NL * ND);

    // producer addressing
    const int fd4  = t & 15;
    const int soff = (fd4 < 8) ? 4 * fd4 : 36 + 4 * (fd4 - 8);
    const int fl0  = t >> 4;             // +32 per chunk
    const int mqq  = t >> 5;             // t<256 only
    const int mli  = (t & 31) * 4;

    // mean accumulators (warps 8..15): 4 queries per lane-half
    ull   accA[4] = {0,0,0,0}, accB[4] = {0,0,0,0};
    float cq[4]   = {0.f,0.f,0.f,0.f};
    const int wm   = wid - 8;
    const int c    = lane & 15;
    const int qg2  = (lane >> 4) * 4;
    const int voff = (c < 8) ? 4 * c : 36 + 4 * (c - 8);

    // score lane layout: 2 keys, d-half, query-half
    const int ks = lane >> 2;
    const int dh = (lane >> 1) & 1;
    const int qh = lane & 1;
    const int k0 = wid * 16 + 2 * ks;
    const float* kb0 = k_s + k0 * KSTR + dh * 36;
    const float* kb1 = kb0 + KSTR;
    const float* qb  = qT + dh * QTH + qh * 4;

    float c0 = 0.f, c1 = 0.f;

    for (int tile = 0; tile < NTILES; ++tile) {
        const int l0 = tile * TK;
        __syncthreads();
        // ---- producer: K then V (batched loads -> stores), mask ----
        {
            float4 a0 = kg4[(size_t)(l0 + fl0      ) * 16 + fd4];
            float4 a1 = kg4[(size_t)(l0 + fl0 + 32 ) * 16 + fd4];
            float4 a2 = kg4[(size_t)(l0 + fl0 + 64 ) * 16 + fd4];
            float4 a3 = kg4[(size_t)(l0 + fl0 + 96 ) * 16 + fd4];
            *(float4*)(k_s + (fl0      ) * KSTR + soff) = a0;
            *(float4*)(k_s + (fl0 + 32 ) * KSTR + soff) = a1;
            *(float4*)(k_s + (fl0 + 64 ) * KSTR + soff) = a2;
            *(float4*)(k_s + (fl0 + 96 ) * KSTR + soff) = a3;
            float4 b0 = vg4[(size_t)(l0 + fl0      ) * 16 + fd4];
            float4 b1 = vg4[(size_t)(l0 + fl0 + 32 ) * 16 + fd4];
            float4 b2 = vg4[(size_t)(l0 + fl0 + 64 ) * 16 + fd4];
            float4 b3 = vg4[(size_t)(l0 + fl0 + 96 ) * 16 + fd4];
            *(float4*)(v_s + (fl0      ) * KSTR + soff) = b0;
            *(float4*)(v_s + (fl0 + 32 ) * KSTR + soff) = b1;
            *(float4*)(v_s + (fl0 + 64 ) * KSTR + soff) = b2;
            *(float4*)(v_s + (fl0 + 96 ) * KSTR + soff) = b3;
        }
        if (t < 256) {
            size_t base = ((size_t)(b * NLQ + q0 + mqq)) * NL + l0 + mli;
            float4 mv;
            if (mode == 0) {
                uchar4 u = *(const uchar4*)((const unsigned char*)maskg + base);
                mv = make_float4(u.x ? 1.f : 0.f, u.y ? 1.f : 0.f,
                                 u.z ? 1.f : 0.f, u.w ? 1.f : 0.f);
            } else if (mode == 1) {
                int4 u = *(const int4*)((const int*)maskg + base);
                mv = make_float4(u.x ? 1.f : 0.f, u.y ? 1.f : 0.f,
                                 u.z ? 1.f : 0.f, u.w ? 1.f : 0.f);
            } else {
                mv = *(const float4*)((const float*)maskg + base);
            }
            *(float4*)(m_s + mqq * MSTR + mli) = mv;
        }
        __syncthreads();

        if (wid < 8) {
            // ---- scores: 2 keys x 4 queries x 32 dims per lane ----
            ull a00 = 0, a01 = 0, a10 = 0, a11 = 0;
            #pragma unroll
            for (int s = 0; s < 8; ++s) {
                float4 ka = *(const float4*)(kb0 + 4 * s);
                float4 kc = *(const float4*)(kb1 + 4 * s);
                #pragma unroll
                for (int j = 0; j < 4; ++j) {
                    ulonglong2 qv = *(const ulonglong2*)(qb + (4 * s + j) * 12);
                    float fa = (j == 0) ? ka.x : (j == 1) ? ka.y : (j == 2) ? ka.z : ka.w;
                    float fc = (j == 0) ? kc.x : (j == 1) ? kc.y : (j == 2) ? kc.z : kc.w;
                    ull pa, pc;
                    F32X2_PACK(pa, fa, fa);
                    F32X2_PACK(pc, fc, fc);
                    F32X2_FMA(a00, pa, qv.x);
                    F32X2_FMA(a01, pa, qv.y);
                    F32X2_FMA(a10, pc, qv.x);
                    F32X2_FMA(a11, pc, qv.y);
                }
            }
            ull o;
            o = __shfl_xor_sync(0xffffffffu, a00, 2); F32X2_ADD(a00, a00, o);
            o = __shfl_xor_sync(0xffffffffu, a01, 2); F32X2_ADD(a01, a01, o);
            o = __shfl_xor_sync(0xffffffffu, a10, 2); F32X2_ADD(a10, a10, o);
            o = __shfl_xor_sync(0xffffffffu, a11, 2); F32X2_ADD(a11, a11, o);
            if (dh == 0) {
                float f[8];
                F32X2_UNPACK(f[0], f[1], a00);
                F32X2_UNPACK(f[2], f[3], a01);
                F32X2_UNPACK(f[4], f[5], a10);
                F32X2_UNPACK(f[6], f[7], a11);
                #pragma unroll
                for (int kk = 0; kk < 2; ++kk) {
                    const int key = k0 + kk;
                    #pragma unroll
                    for (int qi = 0; qi < 4; ++qi) {
                        const int q = 4 * qh + qi;
                        float m = m_s[q * MSTR + key];
                        gsc[q * NL + l0 + key] =
                            (m != 0.f) ? f[kk * 4 + qi] * 0.125f : -FLT_MAX;
                    }
                }
            }
        } else {
            // ---- masked mean: 16 keys x 4 queries x 4 dims per lane ----
            const int lb = wm * 16;
            #pragma unroll
            for (int sb = 0; sb < 4; ++sb) {
                float4 m0 = *(const float4*)(m_s + (qg2 + 0) * MSTR + lb + 4 * sb);
                float4 m1 = *(const float4*)(m_s + (qg2 + 1) * MSTR + lb + 4 * sb);
                float4 m2 = *(const float4*)(m_s + (qg2 + 2) * MSTR + lb + 4 * sb);
                float4 m3 = *(const float4*)(m_s + (qg2 + 3) * MSTR + lb + 4 * sb);
                #pragma unroll
                for (int sk = 0; sk < 4; ++sk) {
                    ulonglong2 vv = *(const ulonglong2*)
                        (v_s + (lb + 4 * sb + sk) * KSTR + voff);
                    float mm0 = (sk == 0) ? m0.x : (sk == 1) ? m0.y : (sk == 2) ? m0.z : m0.w;
                    float mm1 = (sk == 0) ? m1.x : (sk == 1) ? m1.y : (sk == 2) ? m1.z : m1.w;
                    float mm2 = (sk == 0) ? m2.x : (sk == 1) ? m2.y : (sk == 2) ? m2.z : m2.w;
                    float mm3 = (sk == 0) ? m3.x : (sk == 1) ? m3.y : (sk == 2) ? m3.z : m3.w;
                    ull pm;
                    F32X2_PACK(pm, mm0, mm0);
                    F32X2_FMA(accA[0], pm, vv.x); F32X2_FMA(accB[0], pm, vv.y);
                    F32X2_PACK(pm, mm1, mm1);
                    F32X2_FMA(accA[1], pm, vv.x); F32X2_FMA(accB[1], pm, vv.y);
                    F32X2_PACK(pm, mm2, mm2);
                    F32X2_FMA(accA[2], pm, vv.x); F32X2_FMA(accB[2], pm, vv.y);
                    F32X2_PACK(pm, mm3, mm3);
                    F32X2_FMA(accA[3], pm, vv.x); F32X2_FMA(accB[3], pm, vv.y);
                    if (c == 0) {
                        cq[0] += mm0; cq[1] += mm1; cq[2] += mm2; cq[3] += mm3;
                    }
                }
            }
        }
    }

    __syncthreads();   // all scores globally visible; smem K/V free

    if (wid >= 8) {
        // publish per-warp mean partials into dead v_s space
        float* pbuf = v_s + wm * 1152;
        #pragma unroll
        for (int j = 0; j < 4; ++j) {
            float g0, g1, g2, g3;
            F32X2_UNPACK(g0, g1, accA[j]);
            F32X2_UNPACK(g2, g3, accB[j]);
            *(float4*)(pbuf + (qg2 + j) * ND + 4 * c) = make_float4(g0, g1, g2, g3);
        }
        if (c == 0) {
            #pragma unroll
            for (int j = 0; j < 4; ++j) pbuf[512 + qg2 + j] = cq[j];
        }
        asm volatile("bar.sync 1, 256;" ::: "memory");
        const int idx = wm * 32 + lane;   // 0..255
        #pragma unroll
        for (int r = 0; r < 2; ++r) {
            const int jx = idx * 2 + r;
            float s = 0.f;
            #pragma unroll
            for (int p = 0; p < 8; ++p) s += v_s[p * 1152 + jx];
            msum[jx] = s;
        }
        if (idx < 8) {
            float s = 0.f;
            #pragma unroll
            for (int p = 0; p < 8; ++p) s += v_s[p * 1152 + 512 + idx];
            cnts[idx] = s;
        }
    } else {
        // ---- top-32 + softmax + gather for query q = wid (scores in L2) ----
        const int q = wid;
        const float* row = gsc + q * NL;

        float v0 = -FLT_MAX, v1 = -FLT_MAX, v2 = -FLT_MAX, v3 = -FLT_MAX;
        int   i0 = NL, i1 = NL, i2 = NL, i3 = NL;
        for (int i = lane; i < NL; i += 32) {
            float x = row[i];
            if (x > v3) {
                if (x > v1) {
                    if (x > v0) { v3=v2;i3=i2; v2=v1;i2=i1; v1=v0;i1=i0; v0=x;i0=i; }
                    else        { v3=v2;i3=i2; v2=v1;i2=i1; v1=x;i1=i; }
                } else {
                    if (x > v2) { v3=v2;i3=i2; v2=x;i2=i; }
                    else        { v3=x;i3=i; }
                }
            }
        }

        float myval = -FLT_MAX;
        int   myidx = NL;
        for (int s = 0; s < 32; ++s) {
            float cv = v0; int ci = i0;
            #pragma unroll
            for (int off = 16; off; off >>= 1) {
                float ov = __shfl_xor_sync(0xffffffffu, cv, off);
                int   oi = __shfl_xor_sync(0xffffffffu, ci, off);
                if (ov > cv || (ov == cv && oi < ci)) { cv = ov; ci = oi; }
            }
            if (lane == s) { myval = cv; myidx = ci; }
            if (v0 == cv && i0 == ci) {
                v0 = v1; i0 = i1; v1 = v2; i1 = i2; v2 = v3; i2 = i3;
                v3 = -FLT_MAX; i3 = NL;
                if (v0 == -FLT_MAX && cv > -FLT_MAX) {
                    float nv = -FLT_MAX; int ni = NL;
                    for (int i = lane; i < NL; i += 32) {
                        float x = row[i];
                        if (x < cv && x > nv) { nv = x; ni = i; }
                    }
                    v0 = nv; i0 = ni;
                }
            }
        }

        bool  valid = (myval > -1e37f) && (myidx < NL);
        float mmax  = valid ? myval : -FLT_MAX;
        #pragma unroll
        for (int off = 16; off; off >>= 1)
            mmax = fmaxf(mmax, __shfl_xor_sync(0xffffffffu, mmax, off));
        float e  = valid ? __expf(myval - mmax) : 0.f;
        float es = e;
        #pragma unroll
        for (int off = 16; off; off >>= 1)
            es += __shfl_xor_sync(0xffffffffu, es, off);
        float attn = (es > 0.f) ? e / es : 0.f;

        const float* vb = vg + (size_t)b * NL * ND;
        #pragma unroll 4
        for (int i = 0; i < 32; ++i) {
            float a   = __shfl_sync(0xffffffffu, attn,  i);
            int   idx = __shfl_sync(0xffffffffu, myidx, i);
            if (a > 0.f && idx < NL) {
                const float* vr2 = vb + (size_t)idx * ND;
                c0 += a * vr2[lane];
                c1 += a * vr2[lane + 32];
            }
        }
    }
    __syncthreads();

    if (wid < 8) {
        const int q = wid;
        float cdiv = fmaxf(cnts[q], 1.f);
        size_t orow = ((size_t)(b * NLQ + q0 + q)) * ND;
        out[orow + lane]      = msum[q * ND + lane]      / cdiv + c0;
        out[orow + lane + 32] = msum[q * ND + lane + 32] / cdiv + c1;
    }
}

extern "C" void kernel_launch(void* const* d_in, const int* in_sizes, int n_in,
                              void* d_out, int out_size) {
    const float* q    = (const float*)d_in[0];
    const float* k    = (const float*)d_in[1];
    const float* v    = (const float*)d_in[2];
    const void*  mask = d_in[3];
    float* out = (float*)d_out;

    cudaFuncSetAttribute(ga_kernel, cudaFuncAttributeMaxDynamicSharedMemorySize,
                         SMEM_BYTES);

    detect_mask_kernel<<<1, 1>>>((const unsigned int*)mask);
    ga_kernel<<<NCTAS, NTHREADS, SMEM_BYTES>>>(q, k, v, mask, out);
}

// round 6
// speedup vs baseline: 1.3473x; 1.3000x over previous
#include <cuda_runtime.h>
#include <float.h>

typedef unsigned long long ull;

#define NB   8
#define NLQ  512
#define NL   4096
#define ND   64
#define TQ   8
#define NTHREADS 512
#define NCTAS  (NB * (NLQ/TQ))     // 512

#define TKS 128                    // score-group tile
#define NTS (NL/TKS)               // 32
#define TKM 64                     // mean-group tile
#define NTM (NL/TKM)               // 64

#define KSTR 72          // split-d row: d<32 at [4*c8], d>=32 at [36+...]
#define VSTR 64          // V rows unpadded
#define QTH  392         // qT d-half block stride (32*12 + 8)
#define NWORDS (NL/32)   // 128 mask words per row

// smem offsets (floats)
#define OFF_KS   0                             // 2*128*72 = 18432
#define OFF_VS   (OFF_KS + 2*TKS*KSTR)         // 2*64*64  = 8192
#define OFF_KM   (OFF_VS + 2*TKM*VSTR)         // 64 words
#define OFF_VM   (OFF_KM + 64)                 // 32 words
#define OFF_QT   (OFF_VM + 32)                 // 784
#define OFF_MSUM (OFF_QT + 2*QTH)              // 512
#define OFF_CNT  (OFF_MSUM + TQ*ND)            // 8
#define SMEM_FLOATS (OFF_CNT + TQ)             // 28024
#define SMEM_BYTES  (SMEM_FLOATS * 4)          // 112096 -> 2 CTAs/SM

// packed fp32x2 ops (sm_103a)
#define F32X2_FMA(d,a,b)  asm("fma.rn.f32x2 %0, %1, %2, %0;" : "+l"(d) : "l"(a), "l"(b))
#define F32X2_ADD(d,a,b)  asm("add.rn.f32x2 %0, %1, %2;"     : "=l"(d) : "l"(a), "l"(b))
#define F32X2_PACK(d,lo,hi)   asm("mov.b64 %0, {%1, %2};" : "=l"(d) : "f"(lo), "f"(hi))
#define F32X2_UNPACK(lo,hi,s) asm("mov.b64 {%0, %1}, %2;" : "=f"(lo), "=f"(hi) : "l"(s))

#define ONE2 0x3F8000003F800000ULL

__device__ __forceinline__ void cp16(void* s, const void* g) {
    unsigned sa = (unsigned)__cvta_generic_to_shared(s);
    asm volatile("cp.async.cg.shared.global [%0], [%1], 16;" :: "r"(sa), "l"(g));
}
__device__ __forceinline__ void cp8(void* s, const void* g) {
    unsigned sa = (unsigned)__cvta_generic_to_shared(s);
    asm volatile("cp.async.ca.shared.global [%0], [%1], 8;" :: "r"(sa), "l"(g));
}
#define CP_COMMIT() asm volatile("cp.async.commit_group;" ::: "memory")
#define CP_WAIT0()  asm volatile("cp.async.wait_group 0;" ::: "memory")
#define BARG(id)    asm volatile("bar.sync %0, 256;" :: "r"(id) : "memory")

// global scratch
__device__ float    g_sc[(size_t)NCTAS * TQ * NL];      // 64 MB (L2-resident per wave)
__device__ unsigned g_mbits[(size_t)NB * NLQ * NWORDS]; // 2 MB bit mask
__device__ int      g_mask_mode;                        // 0=u8, 1=i32, 2=f32

__global__ void detect_mask_kernel(const unsigned int* __restrict__ m) {
    int allle1 = 1, allf = 1;
    for (int i = 0; i < 32; ++i) {
        unsigned w = m[i];
        if (w > 1u) allle1 = 0;
        if (w != 0u && w != 0x3F800000u) allf = 0;
    }
    g_mask_mode = allf ? 2 : (allle1 ? 1 : 0);
}

// pack mask -> bits: one thread builds one 32-bit word
__global__ __launch_bounds__(256)
void maskbits_kernel(const void* __restrict__ mg) {
    int tid = blockIdx.x * 256 + threadIdx.x;      // 0 .. 524287
    unsigned w = 0;
    if (g_mask_mode == 0) {
        const uint4* p = (const uint4*)((const char*)mg + (size_t)tid * 32);
        uint4 a = p[0], b2 = p[1];
        unsigned v[8] = {a.x, a.y, a.z, a.w, b2.x, b2.y, b2.z, b2.w};
        #pragma unroll
        for (int i = 0; i < 8; ++i)
            #pragma unroll
            for (int j = 0; j < 4; ++j)
                w |= (((v[i] >> (8 * j)) & 0xFFu) ? 1u : 0u) << (i * 4 + j);
    } else {
        const uint4* p = (const uint4*)((const char*)mg + (size_t)tid * 128);
        #pragma unroll
        for (int i = 0; i < 8; ++i) {
            uint4 x = p[i];
            w |= (x.x ? 1u : 0u) << (i * 4 + 0);
            w |= (x.y ? 1u : 0u) << (i * 4 + 1);
            w |= (x.z ? 1u : 0u) << (i * 4 + 2);
            w |= (x.w ? 1u : 0u) << (i * 4 + 3);
        }
    }
    g_mbits[tid] = w;
}

__global__ __launch_bounds__(NTHREADS, 2)
void ga_kernel(const float* __restrict__ qg, const float* __restrict__ kg,
               const float* __restrict__ vg, float* __restrict__ out)
{
    extern __shared__ float smem[];
    float*    k_s  = smem + OFF_KS;
    float*    v_s  = smem + OFF_VS;
    unsigned* km   = (unsigned*)(smem + OFF_KM);
    unsigned* vm   = (unsigned*)(smem + OFF_VM);
    float*    qT   = smem + OFF_QT;
    float*    msum = smem + OFF_MSUM;
    float*    cnts = smem + OFF_CNT;

    const int t    = threadIdx.x;
    const int wid  = t >> 5;
    const int lane = t & 31;
    const int b    = blockIdx.x >> 6;
    const int q0   = (blockIdx.x & 63) * TQ;

    float* gsc = g_sc + (size_t)blockIdx.x * (TQ * NL);
    const unsigned* mb = g_mbits + (size_t)(b * NLQ + q0) * NWORDS;

    float c0 = 0.f, c1 = 0.f;

    if (wid < 8) {
        // =================== SCORE GROUP (threads 0..255) ===================
        const int t2 = t;
        // stage qT (2 elems/thread): qT[(d>>5)*QTH + (d&31)*12 + q]
        #pragma unroll
        for (int e = 0; e < 2; ++e) {
            int idx = t2 * 2 + e;
            int d = idx >> 3, q = idx & 7;
            qT[(d >> 5) * QTH + (d & 31) * 12 + q] =
                qg[((size_t)(b * NLQ + q0 + q)) * ND + d];
        }

        const char* kbase = (const char*)(kg + (size_t)b * NL * ND);
        const int fd4  = t2 & 15;
        const int fl0  = t2 >> 4;
        const int soff = (fd4 < 8) ? 4 * fd4 : 36 + 4 * (fd4 - 8);

        // issue K tile + mask words async
        {
            float* kd = k_s;    // buf 0
            #pragma unroll
            for (int r = 0; r < 8; ++r) {
                int row = fl0 + 16 * r;
                cp16(kd + row * KSTR + soff,
                     kbase + (size_t)(0 * TKS + row) * 256 + fd4 * 16);
            }
            if (t2 < 8) cp16(km + t2 * 4, mb + t2 * NWORDS + 0);
            CP_COMMIT();
        }

        // lane layout: 2 keys, d-half, query-half
        const int ks = lane >> 2;
        const int dh = (lane >> 1) & 1;
        const int qh = lane & 1;
        const int k0 = wid * 16 + 2 * ks;         // local key in tile
        const int kword = wid >> 1;               // key>>5, constant per warp
        const float* qb = qT + dh * QTH + qh * 4;

        for (int tile = 0; tile < NTS; ++tile) {
            CP_WAIT0();
            BARG(1);
            if (tile + 1 < NTS) {
                float* kd = k_s + ((tile + 1) & 1) * (TKS * KSTR);
                #pragma unroll
                for (int r = 0; r < 8; ++r) {
                    int row = fl0 + 16 * r;
                    cp16(kd + row * KSTR + soff,
                         kbase + (size_t)((tile + 1) * TKS + row) * 256 + fd4 * 16);
                }
                if (t2 < 8)
                    cp16(km + ((tile + 1) & 1) * 32 + t2 * 4,
                         mb + t2 * NWORDS + (tile + 1) * 4);
                CP_COMMIT();
            }

            const float* kb = k_s + (tile & 1) * (TKS * KSTR);
            const float* kb0 = kb + k0 * KSTR + dh * 36;
            const float* kb1 = kb0 + KSTR;
            ull a00 = 0, a01 = 0, a10 = 0, a11 = 0;
            #pragma unroll
            for (int s = 0; s < 8; ++s) {
                float4 ka = *(const float4*)(kb0 + 4 * s);
                float4 kc = *(const float4*)(kb1 + 4 * s);
                #pragma unroll
                for (int j = 0; j < 4; ++j) {
                    ulonglong2 qv = *(const ulonglong2*)(qb + (4 * s + j) * 12);
                    float fa = (j == 0) ? ka.x : (j == 1) ? ka.y : (j == 2) ? ka.z : ka.w;
                    float fc = (j == 0) ? kc.x : (j == 1) ? kc.y : (j == 2) ? kc.z : kc.w;
                    ull pa, pc;
                    F32X2_PACK(pa, fa, fa);
                    F32X2_PACK(pc, fc, fc);
                    F32X2_FMA(a00, pa, qv.x);
                    F32X2_FMA(a01, pa, qv.y);
                    F32X2_FMA(a10, pc, qv.x);
                    F32X2_FMA(a11, pc, qv.y);
                }
            }
            ull o;
            o = __shfl_xor_sync(0xffffffffu, a00, 2); F32X2_ADD(a00, a00, o);
            o = __shfl_xor_sync(0xffffffffu, a01, 2); F32X2_ADD(a01, a01, o);
            o = __shfl_xor_sync(0xffffffffu, a10, 2); F32X2_ADD(a10, a10, o);
            o = __shfl_xor_sync(0xffffffffu, a11, 2); F32X2_ADD(a11, a11, o);
            if (dh == 0) {
                float f[8];
                F32X2_UNPACK(f[0], f[1], a00);
                F32X2_UNPACK(f[2], f[3], a01);
                F32X2_UNPACK(f[4], f[5], a10);
                F32X2_UNPACK(f[6], f[7], a11);
                const unsigned* kmc = km + (tile & 1) * 32;
                const int l0 = tile * TKS;
                #pragma unroll
                for (int kk = 0; kk < 2; ++kk) {
                    const int key = k0 + kk;
                    #pragma unroll
                    for (int qi = 0; qi < 4; ++qi) {
                        const int q = 4 * qh + qi;
                        unsigned w = kmc[q * 4 + kword];
                        unsigned bit = (w >> (key & 31)) & 1u;
                        gsc[q * NL + l0 + key] =
                            bit ? f[kk * 4 + qi] * 0.125f : -FLT_MAX;
                    }
                }
            }
        }

        __threadfence_block();
        BARG(1);   // all scores visible to score group

        // ---- top-32 + softmax + gather for query q = wid ----
        const int q = wid;
        const float* row = gsc + q * NL;

        float v0 = -FLT_MAX, v1 = -FLT_MAX, v2 = -FLT_MAX, v3 = -FLT_MAX;
        int   i0 = NL, i1 = NL, i2 = NL, i3 = NL;
        for (int i = lane; i < NL; i += 32) {
            float x = row[i];
            if (x > v3) {
                if (x > v1) {
                    if (x > v0) { v3=v2;i3=i2; v2=v1;i2=i1; v1=v0;i1=i0; v0=x;i0=i; }
                    else        { v3=v2;i3=i2; v2=v1;i2=i1; v1=x;i1=i; }
                } else {
                    if (x > v2) { v3=v2;i3=i2; v2=x;i2=i; }
                    else        { v3=x;i3=i; }
                }
            }
        }

        float myval = -FLT_MAX;
        int   myidx = NL;
        for (int s = 0; s < 32; ++s) {
            float cv = v0; int ci = i0;
            #pragma unroll
            for (int off = 16; off; off >>= 1) {
                float ov = __shfl_xor_sync(0xffffffffu, cv, off);
                int   oi = __shfl_xor_sync(0xffffffffu, ci, off);
                if (ov > cv || (ov == cv && oi < ci)) { cv = ov; ci = oi; }
            }
            if (lane == s) { myval = cv; myidx = ci; }
            if (v0 == cv && i0 == ci) {
                v0 = v1; i0 = i1; v1 = v2; i1 = i2; v2 = v3; i2 = i3;
                v3 = -FLT_MAX; i3 = NL;
                if (v0 == -FLT_MAX && cv > -FLT_MAX) {
                    float nv = -FLT_MAX; int ni = NL;
                    for (int i = lane; i < NL; i += 32) {
                        float x = row[i];
                        if (x < cv && x > nv) { nv = x; ni = i; }
                    }
                    v0 = nv; i0 = ni;
                }
            }
        }

        bool  valid = (myval > -1e37f) && (myidx < NL);
        float mmax  = valid ? myval : -FLT_MAX;
        #pragma unroll
        for (int off = 16; off; off >>= 1)
            mmax = fmaxf(mmax, __shfl_xor_sync(0xffffffffu, mmax, off));
        float e  = valid ? __expf(myval - mmax) : 0.f;
        float es = e;
        #pragma unroll
        for (int off = 16; off; off >>= 1)
            es += __shfl_xor_sync(0xffffffffu, es, off);
        float attn = (es > 0.f) ? e / es : 0.f;

        const float* vb = vg + (size_t)b * NL * ND;
        #pragma unroll 4
        for (int i = 0; i < 32; ++i) {
            float a   = __shfl_sync(0xffffffffu, attn,  i);
            int   idx = __shfl_sync(0xffffffffu, myidx, i);
            if (a > 0.f && idx < NL) {
                const float* vr2 = vb + (size_t)idx * ND;
                c0 += a * vr2[lane];
                c1 += a * vr2[lane + 32];
            }
        }
    } else {
        // =================== MEAN GROUP (threads 256..511) ==================
        const int t2 = t - 256;
        const int wm = wid - 8;

        const char* vbase = (const char*)(vg + (size_t)b * NL * ND);
        const int fd4 = t2 & 15;
        const int fl0 = t2 >> 4;

        {
            #pragma unroll
            for (int r = 0; r < 4; ++r) {
                int row = fl0 + 16 * r;
                cp16(v_s + row * VSTR + fd4 * 4,
                     vbase + (size_t)(0 * TKM + row) * 256 + fd4 * 16);
            }
            if (t2 < 8) cp8(vm + t2 * 2, mb + t2 * NWORDS + 0);
            CP_COMMIT();
        }

        const int c   = lane & 15;
        const int qg2 = (lane >> 4) * 4;
        const int lb  = wm * 8;                 // local row base
        const int wsel = wm >> 2;               // word within tile
        const int shb  = (wm * 8) & 31;         // shift base

        ull accA[4] = {0,0,0,0}, accB[4] = {0,0,0,0};

        for (int tile = 0; tile < NTM; ++tile) {
            CP_WAIT0();
            BARG(2);
            if (tile + 1 < NTM) {
                float* vd = v_s + ((tile + 1) & 1) * (TKM * VSTR);
                #pragma unroll
                for (int r = 0; r < 4; ++r) {
                    int row = fl0 + 16 * r;
                    cp16(vd + row * VSTR + fd4 * 4,
                         vbase + (size_t)((tile + 1) * TKM + row) * 256 + fd4 * 16);
                }
                if (t2 < 8)
                    cp8(vm + ((tile + 1) & 1) * 16 + t2 * 2,
                        mb + t2 * NWORDS + (tile + 1) * 2);
                CP_COMMIT();
            }

            const float* vbuf = v_s + (tile & 1) * (TKM * VSTR);
            const unsigned* vmc = vm + (tile & 1) * 16;
            unsigned wq0 = vmc[(qg2 + 0) * 2 + wsel];
            unsigned wq1 = vmc[(qg2 + 1) * 2 + wsel];
            unsigned wq2 = vmc[(qg2 + 2) * 2 + wsel];
            unsigned wq3 = vmc[(qg2 + 3) * 2 + wsel];
            #pragma unroll
            for (int r = 0; r < 8; ++r) {
                ulonglong2 vv = *(const ulonglong2*)(vbuf + (lb + r) * VSTR + 4 * c);
                ull pm;
                pm = ((wq0 >> (shb + r)) & 1u) ? ONE2 : 0ULL;
                F32X2_FMA(accA[0], pm, vv.x); F32X2_FMA(accB[0], pm, vv.y);
                pm = ((wq1 >> (shb + r)) & 1u) ? ONE2 : 0ULL;
                F32X2_FMA(accA[1], pm, vv.x); F32X2_FMA(accB[1], pm, vv.y);
                pm = ((wq2 >> (shb + r)) & 1u) ? ONE2 : 0ULL;
                F32X2_FMA(accA[2], pm, vv.x); F32X2_FMA(accB[2], pm, vv.y);
                pm = ((wq3 >> (shb + r)) & 1u) ? ONE2 : 0ULL;
                F32X2_FMA(accA[3], pm, vv.x); F32X2_FMA(accB[3], pm, vv.y);
            }
        }

        // publish per-warp partials into v_s scratch (group is done with tiles)
        BARG(2);
        float* pbuf = v_s + wm * 520;
        #pragma unroll
        for (int j = 0; j < 4; ++j) {
            float g0, g1, g2, g3;
            F32X2_UNPACK(g0, g1, accA[j]);
            F32X2_UNPACK(g2, g3, accB[j]);
            *(float4*)(pbuf + (qg2 + j) * ND + 4 * c) = make_float4(g0, g1, g2, g3);
        }
        BARG(2);
        // reduce partials -> msum (512 elems / 256 threads)
        #pragma unroll
        for (int r = 0; r < 2; ++r) {
            const int jx = t2 * 2 + r;
            float s = 0.f;
            #pragma unroll
            for (int p = 0; p < 8; ++p) s += v_s[p * 520 + jx];
            msum[jx] = s;
        }
        // counts via popc of full mask row (warp wm handles query wm)
        {
            const unsigned* mrow = mb + wm * NWORDS;
            unsigned s = __popc(mrow[lane]) + __popc(mrow[lane + 32]) +
                         __popc(mrow[lane + 64]) + __popc(mrow[lane + 96]);
            #pragma unroll
            for (int off = 16; off; off >>= 1)
                s += __shfl_xor_sync(0xffffffffu, s, off);
            if (lane == 0) cnts[wm] = (float)s;
        }
    }

    __syncthreads();

    if (wid < 8) {
        const int q = wid;
        float cdiv = fmaxf(cnts[q], 1.f);
        size_t orow = ((size_t)(b * NLQ + q0 + q)) * ND;
        out[orow + lane]      = msum[q * ND + lane]      / cdiv + c0;
        out[orow + lane + 32] = msum[q * ND + lane + 32] / cdiv + c1;
    }
}

extern "C" void kernel_launch(void* const* d_in, const int* in_sizes, int n_in,
                              void* d_out, int out_size) {
    const float* q    = (const float*)d_in[0];
    const float* k    = (const float*)d_in[1];
    const float* v    = (const float*)d_in[2];
    const void*  mask = d_in[3];
    float* out = (float*)d_out;

    cudaFuncSetAttribute(ga_kernel, cudaFuncAttributeMaxDynamicSharedMemorySize,
                         SMEM_BYTES);

    detect_mask_kernel<<<1, 1>>>((const unsigned int*)mask);
    maskbits_kernel<<<(NB * NLQ * NWORDS) / 256, 256>>>(mask);
    ga_kernel<<<NCTAS, NTHREADS, SMEM_BYTES>>>(q, k, v, out);
}